// round 13
// baseline (speedup 1.0000x reference)
#include <cuda_runtime.h>
#include <cuda_bf16.h>
#include <mma.h>
#include <cstdint>

using namespace nvcuda;
typedef __nv_bfloat16 bf16;

// ---------------- constants ----------------
// C=768, HEADS=16, CH=48, WIN=8x8, SHIFTED, EPS=1e-5
// B=8, 64x64 -> 32768 tokens, 512 windows x 64 tokens, 16 heads

// ---------------- scratch (device globals; no allocation allowed) ----------------
__device__ bf16  g_yw [32768u*768u];    // LN1-modulated, shifted+windowed, bf16
__device__ bf16  g_qkv[32768u*2304u];   // qkv output (windowed token order)
__device__ bf16  g_ow [32768u*768u];    // attention output (windowed, heads merged)
__device__ bf16  g_po [32768u*768u];    // proj output + bias (windowed)
__device__ bf16  g_zin[32768u*768u];    // LN2-modulated (pixel order)
__device__ bf16  g_h1 [32768u*3072u];   // mlp hidden (silu applied)
__device__ float g_hm [8*768];          // silu(mod@ada_w1+b1)
__device__ float g_m  [8*4608];         // modulation vectors a1,b1,c1,a2,b2,c2
__device__ bf16  g_wqkv [768*2304];
__device__ bf16  g_wproj[768*768];
__device__ bf16  g_w1   [768*3072];
__device__ bf16  g_w2   [3072*768];
__device__ float g_cos[16*64*24];
__device__ float g_sin[16*64*24];

// ---------------- helpers ----------------
__device__ __forceinline__ void block_reduce_192(float& s, float& ss) {
    #pragma unroll
    for (int o = 16; o > 0; o >>= 1) {
        s  += __shfl_xor_sync(0xffffffffu, s,  o);
        ss += __shfl_xor_sync(0xffffffffu, ss, o);
    }
    __shared__ float rs[6], rss[6];
    int warp = threadIdx.x >> 5;
    int lane = threadIdx.x & 31;
    if (lane == 0) { rs[warp] = s; rss[warp] = ss; }
    __syncthreads();
    float a = 0.f, b = 0.f;
    #pragma unroll
    for (int i = 0; i < 6; i++) { a += rs[i]; b += rss[i]; }
    s = a; ss = b;
}

__device__ __forceinline__ uint32_t smem_u32(const void* p) {
    uint32_t r;
    asm("{ .reg .u64 t; cvta.to.shared.u64 t, %1; cvt.u32.u64 %0, t; }" : "=r"(r) : "l"(p));
    return r;
}
__device__ __forceinline__ void cpa16(uint32_t s, const void* g) {
    asm volatile("cp.async.cg.shared.global [%0], [%1], 16;" :: "r"(s), "l"(g));
}
__device__ __forceinline__ void cpa_commit() { asm volatile("cp.async.commit_group;" ::: "memory"); }

// ---------------- weight conversion (vectorized, 4 elems/thread) ----------------
__device__ __forceinline__ void cvt4(const float* __restrict__ s, bf16* __restrict__ d, int i) {
    float4 v = *(const float4*)(s + i);
    __nv_bfloat162 lo = __floats2bfloat162_rn(v.x, v.y);
    __nv_bfloat162 hi = __floats2bfloat162_rn(v.z, v.w);
    *(uint2*)(d + i) = make_uint2(*(uint32_t*)&lo, *(uint32_t*)&hi);
}

__global__ void k_cvt_qkv(const float* __restrict__ s0, bf16* __restrict__ d0, int n0) {
    int i = (blockIdx.x * 256 + threadIdx.x) * 4;
    if (i < n0) cvt4(s0, d0, i);
}

__global__ void k_cvt_rest(const float* __restrict__ s1, bf16* __restrict__ d1, int n1,
                           const float* __restrict__ s2, bf16* __restrict__ d2, int n2,
                           const float* __restrict__ s3, bf16* __restrict__ d3, int n3) {
    int i = (blockIdx.x * 256 + threadIdx.x) * 4;
    if (i < n1) { cvt4(s1, d1, i); return; }
    i -= n1;
    if (i < n2) { cvt4(s2, d2, i); return; }
    i -= n2;
    if (i < n3) { cvt4(s3, d3, i); }
}

// ---------------- rope table ----------------
__global__ void k_rope_tab(const float* __restrict__ theta) {
    int i = blockIdx.x * 256 + threadIdx.x;   // < 16*64*24 = 24576
    if (i >= 16*64*24) return;
    int j = i % 24;
    int rem = i / 24;
    int l = rem & 63;
    int h = rem >> 6;
    int f = h*24 + j;
    float th = (float)(l >> 3) * theta[f] + (float)(l & 7) * theta[384 + f];
    float s, c;
    sincosf(th, &s, &c);
    g_cos[i] = c; g_sin[i] = s;
}

// ---------------- modulation MLP: k-split blocks (32 cols x 8 k-chunks) ----------------
__global__ void k_mod1(const float* __restrict__ mod, const float* __restrict__ w1,
                       const float* __restrict__ b1) {
    __shared__ float part[8][33];
    int c  = threadIdx.x & 31;
    int kw = threadIdx.x >> 5;
    int col = blockIdx.x * 32 + c;              // grid.x = 24
    int b   = blockIdx.y;                        // 8
    const float* mrow = mod + b * 768;
    float acc = 0.f;
    int k0 = kw * 96;
    #pragma unroll 8
    for (int k = 0; k < 96; k++)
        acc += __ldg(mrow + k0 + k) * __ldg(w1 + (size_t)(k0 + k)*768 + col);
    part[kw][c] = acc;
    __syncthreads();
    if (kw == 0) {
        float s = part[0][c];
        #pragma unroll
        for (int i = 1; i < 8; i++) s += part[i][c];
        float v = s + b1[col];
        g_hm[b*768 + col] = v / (1.f + expf(-v));
    }
}

__global__ void k_mod2(const float* __restrict__ w2, const float* __restrict__ b2) {
    __shared__ float part[8][33];
    int c  = threadIdx.x & 31;
    int kw = threadIdx.x >> 5;
    int col = blockIdx.x * 32 + c;              // grid.x = 144
    int b   = blockIdx.y;                        // 8
    const float* hrow = g_hm + b * 768;
    float acc = 0.f;
    int k0 = kw * 96;
    #pragma unroll 8
    for (int k = 0; k < 96; k++)
        acc += __ldg(hrow + k0 + k) * __ldg(w2 + (size_t)(k0 + k)*4608 + col);
    part[kw][c] = acc;
    __syncthreads();
    if (kw == 0) {
        float s = part[0][c];
        #pragma unroll
        for (int i = 1; i < 8; i++) s += part[i][c];
        g_m[b*4608 + col] = s + b2[col];
    }
}

// ---------------- LN1 + modulate + shift + window partition (192 thr, float4) ----------------
__global__ void k_ln1(const float* __restrict__ x) {
    int t = blockIdx.x;
    int b   = t >> 12;
    int win = (t >> 6) & 63;
    int l   = t & 63;
    int nh = win >> 3, nw = win & 7;
    int wi = l >> 3,  wj = l & 7;
    int si = (nh*8 + wi + 60) & 63;
    int sj = (nw*8 + wj + 60) & 63;
    const float* xr = x + (size_t)(b*4096 + si*64 + sj) * 768u;
    int tid = threadIdx.x;           // 0..191
    int c = tid * 4;
    float4 v = *(const float4*)(xr + c);
    float s  = v.x + v.y + v.z + v.w;
    float ss = v.x*v.x + v.y*v.y + v.z*v.z + v.w*v.w;
    block_reduce_192(s, ss);
    float mean = s * (1.f/768.f);
    float var  = (ss - s*mean) * (1.f/767.f);
    float inv  = rsqrtf(var + 1e-5f);
    const float* mb = g_m + b*4608;
    float4 a1 = *(const float4*)(mb + c);
    float4 b1 = *(const float4*)(mb + 768 + c);
    float o0 = (a1.x + 1.f) * (v.x - mean) * inv + b1.x;
    float o1 = (a1.y + 1.f) * (v.y - mean) * inv + b1.y;
    float o2 = (a1.z + 1.f) * (v.z - mean) * inv + b1.z;
    float o3 = (a1.w + 1.f) * (v.w - mean) * inv + b1.w;
    __nv_bfloat162 lo = __floats2bfloat162_rn(o0, o1);
    __nv_bfloat162 hi = __floats2bfloat162_rn(o2, o3);
    *(uint2*)(g_yw + (size_t)t*768u + c) = make_uint2(*(uint32_t*)&lo, *(uint32_t*)&hi);
}

// ---------------- residual1 + LN2 + modulate (192 thr, float4) ----------------
__global__ void k_resid_ln2(const float* __restrict__ x) {
    int p = blockIdx.x;
    int b = p >> 12;
    int i = (p >> 6) & 63, j = p & 63;
    int hh = (i+4) & 63, ww = (j+4) & 63;
    int t = (b*64 + (hh>>3)*8 + (ww>>3))*64 + (hh&7)*8 + (ww&7);
    const float* xr = x + (size_t)p*768u;
    const bf16* pr = g_po + (size_t)t*768u;
    const float* mb = g_m + b*4608;
    int tid = threadIdx.x;           // 0..191
    int c = tid * 4;
    float4 xv = *(const float4*)(xr + c);
    uint2 pu = *(const uint2*)(pr + c);
    __nv_bfloat162 pa = *reinterpret_cast<__nv_bfloat162*>(&pu.x);
    __nv_bfloat162 pb = *reinterpret_cast<__nv_bfloat162*>(&pu.y);
    float4 c1 = *(const float4*)(mb + 1536 + c);
    float y0 = (xv.x + c1.x * __bfloat162float(pa.x)) * rsqrtf(1.f + c1.x*c1.x);
    float y1 = (xv.y + c1.y * __bfloat162float(pa.y)) * rsqrtf(1.f + c1.y*c1.y);
    float y2 = (xv.z + c1.z * __bfloat162float(pb.x)) * rsqrtf(1.f + c1.z*c1.z);
    float y3 = (xv.w + c1.w * __bfloat162float(pb.y)) * rsqrtf(1.f + c1.w*c1.w);
    float s  = y0 + y1 + y2 + y3;
    float ss = y0*y0 + y1*y1 + y2*y2 + y3*y3;
    block_reduce_192(s, ss);
    float mean = s * (1.f/768.f);
    float var  = (ss - s*mean) * (1.f/767.f);
    float inv  = rsqrtf(var + 1e-5f);
    float4 a2 = *(const float4*)(mb + 2304 + c);
    float4 b2 = *(const float4*)(mb + 3072 + c);
    float o0 = (a2.x + 1.f) * (y0 - mean) * inv + b2.x;
    float o1 = (a2.y + 1.f) * (y1 - mean) * inv + b2.y;
    float o2 = (a2.z + 1.f) * (y2 - mean) * inv + b2.z;
    float o3 = (a2.w + 1.f) * (y3 - mean) * inv + b2.w;
    __nv_bfloat162 lo = __floats2bfloat162_rn(o0, o1);
    __nv_bfloat162 hi = __floats2bfloat162_rn(o2, o3);
    *(uint2*)(g_zin + (size_t)p*768u + c) = make_uint2(*(uint32_t*)&lo, *(uint32_t*)&hi);
}

// ---------------- pipelined wmma GEMM: C = A(MxK) @ B(KxN) + bias, epilogue ----------------
// 128x128 CTA tile, K-stage=64, 3-stage cp.async pipeline, 2x4 warp grid (64x32 per warp).
// Stage: As 128x72x2 (18432) + Bs 64x136x2 (17408) = 35840; 3 stages = 107520; 2 CTAs/SM.
#define GSTAGE   35840
#define GEMM_SMEM (3*GSTAGE)            // 107520

template<int MODE>
__global__ void __launch_bounds__(256, 2)
k_gemm(const bf16* __restrict__ A, const bf16* __restrict__ B,
       const float* __restrict__ bias, void* __restrict__ Cout,
       int M, int N, int K, const float* __restrict__ xres) {
    extern __shared__ __align__(128) char dsm[];

    int tid = threadIdx.x;
    int warp = tid >> 5;
    int wr = warp >> 2, wc = warp & 3;      // 2 x 4 warp grid, warp tile 64x32
    int m0 = blockIdx.y * 128, n0 = blockIdx.x * 128;

    const bf16* Ag = A + (size_t)m0 * (size_t)K;

    // per-thread load coords (each cpa16 moves 16 bytes = 8 bf16)
    int arow = tid >> 2;                 // A: 64 rows per pass, 2 passes
    int ach  = (tid & 3) * 16;           //    4 threads x 16 elems (2 cpa16) = 64 k-cols
    int brow = tid >> 4;                 // B: 16 rows per pass, 4 passes
    int bch  = (tid & 15) * 8;           //    16 threads x 8 elems = 128 n-cols

    uint32_t sbase = smem_u32(dsm);

    auto load_stage = [&](int buf, int k0) {
        uint32_t as = sbase + buf * GSTAGE;
        uint32_t bs = as + 18432;
        #pragma unroll
        for (int i = 0; i < 2; i++) {
            int r = arow + i*64;
            const bf16* Ap = Ag + (size_t)r * K + k0 + ach;
            cpa16(as + (r*72 + ach)*2, Ap);
            cpa16(as + (r*72 + ach + 8)*2, Ap + 8);
        }
        #pragma unroll
        for (int i = 0; i < 4; i++) {
            int r = brow + i*16;
            cpa16(bs + (r*136 + bch)*2, B + (size_t)(k0 + r) * N + n0 + bch);
        }
    };

    wmma::fragment<wmma::accumulator, 16,16,16, float> acc[4][2];
    #pragma unroll
    for (int i = 0; i < 4; i++)
        #pragma unroll
        for (int j = 0; j < 2; j++)
            wmma::fill_fragment(acc[i][j], 0.f);

    int KS = K >> 6;   // 64-wide K stages
    load_stage(0, 0);   cpa_commit();
    load_stage(1, 64);  cpa_commit();

    for (int ks = 0; ks < KS; ks++) {
        asm volatile("cp.async.wait_group 1;" ::: "memory");
        __syncthreads();
        int buf = ks % 3;
        bf16* As = (bf16*)(dsm + buf * GSTAGE);
        bf16* Bs = (bf16*)(dsm + buf * GSTAGE + 18432);
        #pragma unroll
        for (int kk = 0; kk < 4; kk++) {
            wmma::fragment<wmma::matrix_a,16,16,16,bf16,wmma::row_major> af[4];
            wmma::fragment<wmma::matrix_b,16,16,16,bf16,wmma::row_major> bfr[2];
            #pragma unroll
            for (int i = 0; i < 4; i++)
                wmma::load_matrix_sync(af[i], &As[(wr*64 + 16*i)*72 + kk*16], 72);
            #pragma unroll
            for (int j = 0; j < 2; j++)
                wmma::load_matrix_sync(bfr[j], &Bs[(kk*16)*136 + wc*32 + 16*j], 136);
            #pragma unroll
            for (int i = 0; i < 4; i++)
                #pragma unroll
                for (int j = 0; j < 2; j++)
                    wmma::mma_sync(acc[i][j], af[i], bfr[j], acc[i][j]);
        }
        int t = ks + 2;
        if (t < KS) load_stage(t % 3, t * 64);
        cpa_commit();
    }
    __syncthreads();   // all warps done before smem reuse

    // epilogue via smem: two halves
    float* Cs = (float*)dsm;   // [64][132]
    #pragma unroll
    for (int half = 0; half < 2; half++) {
        if (wr == half) {
            #pragma unroll
            for (int i = 0; i < 4; i++)
                #pragma unroll
                for (int j = 0; j < 2; j++)
                    wmma::store_matrix_sync(&Cs[(16*i)*132 + wc*32 + 16*j], acc[i][j],
                                            132, wmma::mem_row_major);
        }
        __syncthreads();
        int r  = tid >> 2;
        int cs = (tid & 3) * 32;
        int grow = m0 + half*64 + r;
        #pragma unroll 4
        for (int cc = 0; cc < 32; cc += 2) {
            int col = cs + cc, gcol = n0 + col;
            float v0 = Cs[r*132 + col]     + bias[gcol];
            float v1 = Cs[r*132 + col + 1] + bias[gcol + 1];
            if (MODE == 2) {
                v0 = v0 / (1.f + __expf(-v0));
                v1 = v1 / (1.f + __expf(-v1));
            }
            if (MODE == 3) {
                float c2a = g_m[(grow >> 12)*4608 + 3840 + gcol];
                float c2b = g_m[(grow >> 12)*4608 + 3840 + gcol + 1];
                float o0 = (xres[(size_t)grow*768u + gcol]     + c2a*v0) * rsqrtf(1.f + c2a*c2a);
                float o1 = (xres[(size_t)grow*768u + gcol + 1] + c2b*v1) * rsqrtf(1.f + c2b*c2b);
                *(float2*)((float*)Cout + (size_t)grow*(size_t)N + gcol) = make_float2(o0, o1);
            } else {
                *(__nv_bfloat162*)((bf16*)Cout + (size_t)grow*(size_t)N + gcol) =
                    __floats2bfloat162_rn(v0, v1);
            }
        }
        __syncthreads();
    }
}

// ---------------- window attention: one block per (window, head) ----------------
__global__ void k_attn() {
    __shared__ __align__(128) char smem[35840];
    bf16*  qs = (bf16*)smem;                 // [64][48]
    bf16*  ks = (bf16*)(smem + 6144);        // [64][48]
    bf16*  vs = (bf16*)(smem + 12288);       // [64][48]
    float* Ss = (float*)(smem + 18432);      // [64][68]
    bf16*  Ps = (bf16*)smem;                 // [64][64]
    float* Os = (float*)(smem + 18432);      // [64][48]

    int blk = blockIdx.x;
    int w = blk >> 4, h = blk & 15;
    int tid = threadIdx.x, warp = tid >> 5;
    const float scale = 0.14433756729740643f;   // 1/sqrt(48)

    for (int idx = tid; idx < 1536; idx += 256) {
        int l = idx / 24, j = idx - l*24;
        size_t base = (size_t)(w*64 + l)*2304u + (size_t)h*48u;
        float qr = __bfloat162float(g_qkv[base + 2*j]);
        float qi = __bfloat162float(g_qkv[base + 2*j + 1]);
        float kr = __bfloat162float(g_qkv[base + 768 + 2*j]);
        float ki = __bfloat162float(g_qkv[base + 768 + 2*j + 1]);
        int ti = (h*64 + l)*24 + j;
        float cn = g_cos[ti], sn = g_sin[ti];
        qs[l*48 + 2*j]     = __float2bfloat16((qr*cn - qi*sn) * scale);
        qs[l*48 + 2*j + 1] = __float2bfloat16((qr*sn + qi*cn) * scale);
        ks[l*48 + 2*j]     = __float2bfloat16(kr*cn - ki*sn);
        ks[l*48 + 2*j + 1] = __float2bfloat16(kr*sn + ki*cn);
    }
    for (int idx = tid; idx < 3072; idx += 256) {
        int l = idx / 48, c = idx - l*48;
        vs[idx] = g_qkv[(size_t)(w*64 + l)*2304u + 1536u + h*48u + c];
    }
    __syncthreads();

    #pragma unroll
    for (int tset = 0; tset < 2; tset++) {
        int tile = warp + tset*8;
        int ti = tile >> 2, tj = tile & 3;
        wmma::fragment<wmma::accumulator,16,16,16,float> sacc;
        wmma::fill_fragment(sacc, 0.f);
        #pragma unroll
        for (int kk = 0; kk < 3; kk++) {
            wmma::fragment<wmma::matrix_a,16,16,16,bf16,wmma::row_major> af;
            wmma::fragment<wmma::matrix_b,16,16,16,bf16,wmma::col_major> bfr;
            wmma::load_matrix_sync(af,  &qs[ti*16*48 + kk*16], 48);
            wmma::load_matrix_sync(bfr, &ks[tj*16*48 + kk*16], 48);
            wmma::mma_sync(sacc, af, bfr, sacc);
        }
        wmma::store_matrix_sync(&Ss[ti*16*68 + tj*16], sacc, 68, wmma::mem_row_major);
    }
    __syncthreads();

    {
        int l = tid >> 2, sub = tid & 3;
        float* srow = &Ss[l*68];
        float mx = -1e30f;
        #pragma unroll
        for (int q = 0; q < 16; q++) mx = fmaxf(mx, srow[sub*16 + q]);
        mx = fmaxf(mx, __shfl_xor_sync(0xffffffffu, mx, 1));
        mx = fmaxf(mx, __shfl_xor_sync(0xffffffffu, mx, 2));
        float e[16]; float sum = 0.f;
        #pragma unroll
        for (int q = 0; q < 16; q++) { e[q] = __expf(srow[sub*16 + q] - mx); sum += e[q]; }
        sum += __shfl_xor_sync(0xffffffffu, sum, 1);
        sum += __shfl_xor_sync(0xffffffffu, sum, 2);
        float inv = 1.f / sum;
        #pragma unroll
        for (int q = 0; q < 16; q++)
            Ps[l*64 + sub*16 + q] = __float2bfloat16(e[q] * inv);
    }
    __syncthreads();

    for (int tile = warp; tile < 12; tile += 8) {
        int ti = tile / 3, tj = tile - ti*3;
        wmma::fragment<wmma::accumulator,16,16,16,float> oacc;
        wmma::fill_fragment(oacc, 0.f);
        #pragma unroll
        for (int kk = 0; kk < 4; kk++) {
            wmma::fragment<wmma::matrix_a,16,16,16,bf16,wmma::row_major> af;
            wmma::fragment<wmma::matrix_b,16,16,16,bf16,wmma::row_major> bfr;
            wmma::load_matrix_sync(af,  &Ps[ti*16*64 + kk*16], 64);
            wmma::load_matrix_sync(bfr, &vs[kk*16*48 + tj*16], 48);
            wmma::mma_sync(oacc, af, bfr, oacc);
        }
        wmma::store_matrix_sync(&Os[ti*16*48 + tj*16], oacc, 48, wmma::mem_row_major);
    }
    __syncthreads();

    for (int idx = tid; idx < 3072; idx += 256) {
        int l = idx / 48, c = idx - l*48;
        g_ow[(size_t)(w*64 + l)*768u + h*48u + c] = __float2bfloat16(Os[idx]);
    }
}

// ---------------- launch ----------------
extern "C" void kernel_launch(void* const* d_in, const int* in_sizes, int n_in,
                              void* d_out, int out_size) {
    const float* x       = (const float*)d_in[0];
    const float* mod     = (const float*)d_in[1];
    const float* ada_w1  = (const float*)d_in[2];
    const float* ada_b1  = (const float*)d_in[3];
    const float* ada_w2  = (const float*)d_in[4];
    const float* ada_b2  = (const float*)d_in[5];
    const float* theta   = (const float*)d_in[6];
    const float* qkv_w   = (const float*)d_in[7];
    const float* qkv_b   = (const float*)d_in[8];
    const float* proj_w  = (const float*)d_in[9];
    const float* proj_b  = (const float*)d_in[10];
    const float* mlp_w1  = (const float*)d_in[11];
    const float* mlp_b1  = (const float*)d_in[12];
    const float* mlp_w2  = (const float*)d_in[13];
    const float* mlp_b2  = (const float*)d_in[14];
    float* out = (float*)d_out;

    void *p_yw, *p_qkv, *p_ow, *p_po, *p_zin, *p_h1;
    void *p_wqkv, *p_wproj, *p_w1, *p_w2;
    cudaGetSymbolAddress(&p_yw,   g_yw);
    cudaGetSymbolAddress(&p_qkv,  g_qkv);
    cudaGetSymbolAddress(&p_ow,   g_ow);
    cudaGetSymbolAddress(&p_po,   g_po);
    cudaGetSymbolAddress(&p_zin,  g_zin);
    cudaGetSymbolAddress(&p_h1,   g_h1);
    cudaGetSymbolAddress(&p_wqkv, g_wqkv);
    cudaGetSymbolAddress(&p_wproj,g_wproj);
    cudaGetSymbolAddress(&p_w1,   g_w1);
    cudaGetSymbolAddress(&p_w2,   g_w2);

    static bool init_done = false;
    static cudaStream_t s2;
    static cudaEvent_t evF, evJ;
    if (!init_done) {
        cudaFuncSetAttribute(k_gemm<0>, cudaFuncAttributeMaxDynamicSharedMemorySize, GEMM_SMEM);
        cudaFuncSetAttribute(k_gemm<2>, cudaFuncAttributeMaxDynamicSharedMemorySize, GEMM_SMEM);
        cudaFuncSetAttribute(k_gemm<3>, cudaFuncAttributeMaxDynamicSharedMemorySize, GEMM_SMEM);
        cudaStreamCreateWithFlags(&s2, cudaStreamNonBlocking);
        cudaEventCreateWithFlags(&evF, cudaEventDisableTiming);
        cudaEventCreateWithFlags(&evJ, cudaEventDisableTiming);
        init_done = true;
    }

    // fork: side stream converts proj/mlp weights + rope table (round-10 topology)
    cudaEventRecord(evF, 0);
    cudaStreamWaitEvent(s2, evF, 0);
    k_cvt_rest<<<5184, 256, 0, s2>>>(proj_w, (bf16*)p_wproj, 768*768,
                                     mlp_w1, (bf16*)p_w1, 768*3072,
                                     mlp_w2, (bf16*)p_w2, 3072*768);
    k_rope_tab<<<96, 256, 0, s2>>>(theta);
    cudaEventRecord(evJ, s2);

    // main stream: qkv weights, modulation (k-split), LN1, qkv GEMM
    k_cvt_qkv<<<1728, 256>>>(qkv_w, (bf16*)p_wqkv, 768*2304);
    k_mod1<<<dim3(24, 8), 256>>>(mod, ada_w1, ada_b1);
    k_mod2<<<dim3(144, 8), 256>>>(ada_w2, ada_b2);
    k_ln1<<<32768, 192>>>(x);

    // qkv GEMM (32768x768)@(768x2304)
    k_gemm<0><<<dim3(18, 256), 256, GEMM_SMEM>>>((const bf16*)p_yw, (const bf16*)p_wqkv,
                                                 qkv_b, p_qkv, 32768, 2304, 768, nullptr);

    // join: attention needs rope table; proj/mlp need converted weights
    cudaStreamWaitEvent(0, evJ, 0);

    k_attn<<<8192, 256>>>();

    // proj: (32768x768)@(768x768)
    k_gemm<0><<<dim3(6, 256), 256, GEMM_SMEM>>>((const bf16*)p_ow, (const bf16*)p_wproj,
                                                proj_b, p_po, 32768, 768, 768, nullptr);
    k_resid_ln2<<<32768, 192>>>(x);

    // mlp1 + silu: (32768x768)@(768x3072)
    k_gemm<2><<<dim3(24, 256), 256, GEMM_SMEM>>>((const bf16*)p_zin, (const bf16*)p_w1,
                                                 mlp_b1, p_h1, 32768, 3072, 768, nullptr);
    // mlp2 + final residual: (32768x3072)@(3072x768)
    k_gemm<3><<<dim3(6, 256), 256, GEMM_SMEM>>>((const bf16*)p_h1, (const bf16*)p_w2,
                                                mlp_b2, out, 32768, 768, 3072, x);
}

// round 14
// speedup vs baseline: 1.0052x; 1.0052x over previous
#include <cuda_runtime.h>
#include <cuda_bf16.h>
#include <mma.h>
#include <cstdint>

using namespace nvcuda;
typedef __nv_bfloat16 bf16;

// ---------------- constants ----------------
// C=768, HEADS=16, CH=48, WIN=8x8, SHIFTED, EPS=1e-5
// B=8, 64x64 -> 32768 tokens, 512 windows x 64 tokens, 16 heads

// ---------------- scratch (device globals; no allocation allowed) ----------------
__device__ bf16  g_yw [32768u*768u];    // LN1-modulated, shifted+windowed, bf16
__device__ bf16  g_qkv[32768u*2304u];   // qkv output (windowed token order)
__device__ bf16  g_ow [32768u*768u];    // attention output (windowed, heads merged)
__device__ bf16  g_po [32768u*768u];    // proj output + bias (windowed)
__device__ bf16  g_zin[32768u*768u];    // LN2-modulated (pixel order)
__device__ bf16  g_h1 [32768u*3072u];   // mlp hidden (silu applied)
__device__ float g_hm [8*768];          // silu(mod@ada_w1+b1)
__device__ float g_m  [8*4608];         // modulation vectors a1,b1,c1,a2,b2,c2
__device__ bf16  g_wqkv [768*2304];
__device__ bf16  g_wproj[768*768];
__device__ bf16  g_w1   [768*3072];
__device__ bf16  g_w2   [3072*768];
__device__ float g_cos[16*64*24];
__device__ float g_sin[16*64*24];

// ---------------- helpers ----------------
__device__ __forceinline__ void block_reduce_192(float& s, float& ss) {
    #pragma unroll
    for (int o = 16; o > 0; o >>= 1) {
        s  += __shfl_xor_sync(0xffffffffu, s,  o);
        ss += __shfl_xor_sync(0xffffffffu, ss, o);
    }
    __shared__ float rs[6], rss[6];
    int warp = threadIdx.x >> 5;
    int lane = threadIdx.x & 31;
    if (lane == 0) { rs[warp] = s; rss[warp] = ss; }
    __syncthreads();
    float a = 0.f, b = 0.f;
    #pragma unroll
    for (int i = 0; i < 6; i++) { a += rs[i]; b += rss[i]; }
    s = a; ss = b;
}

__device__ __forceinline__ uint32_t smem_u32(const void* p) {
    uint32_t r;
    asm("{ .reg .u64 t; cvta.to.shared.u64 t, %1; cvt.u32.u64 %0, t; }" : "=r"(r) : "l"(p));
    return r;
}
__device__ __forceinline__ void cpa16(uint32_t s, const void* g) {
    asm volatile("cp.async.cg.shared.global [%0], [%1], 16;" :: "r"(s), "l"(g));
}
__device__ __forceinline__ void cpa_commit() { asm volatile("cp.async.commit_group;" ::: "memory"); }

// ---------------- weight conversion (vectorized, 4 elems/thread) ----------------
__device__ __forceinline__ void cvt4(const float* __restrict__ s, bf16* __restrict__ d, int i) {
    float4 v = *(const float4*)(s + i);
    __nv_bfloat162 lo = __floats2bfloat162_rn(v.x, v.y);
    __nv_bfloat162 hi = __floats2bfloat162_rn(v.z, v.w);
    *(uint2*)(d + i) = make_uint2(*(uint32_t*)&lo, *(uint32_t*)&hi);
}

__global__ void k_cvt_qkv(const float* __restrict__ s0, bf16* __restrict__ d0, int n0) {
    int i = (blockIdx.x * 256 + threadIdx.x) * 4;
    if (i < n0) cvt4(s0, d0, i);
}

__global__ void k_cvt_rest(const float* __restrict__ s1, bf16* __restrict__ d1, int n1,
                           const float* __restrict__ s2, bf16* __restrict__ d2, int n2,
                           const float* __restrict__ s3, bf16* __restrict__ d3, int n3) {
    int i = (blockIdx.x * 256 + threadIdx.x) * 4;
    if (i < n1) { cvt4(s1, d1, i); return; }
    i -= n1;
    if (i < n2) { cvt4(s2, d2, i); return; }
    i -= n2;
    if (i < n3) { cvt4(s3, d3, i); }
}

// ---------------- rope table ----------------
__global__ void k_rope_tab(const float* __restrict__ theta) {
    int i = blockIdx.x * 256 + threadIdx.x;   // < 16*64*24 = 24576
    if (i >= 16*64*24) return;
    int j = i % 24;
    int rem = i / 24;
    int l = rem & 63;
    int h = rem >> 6;
    int f = h*24 + j;
    float th = (float)(l >> 3) * theta[f] + (float)(l & 7) * theta[384 + f];
    float s, c;
    sincosf(th, &s, &c);
    g_cos[i] = c; g_sin[i] = s;
}

// ---------------- modulation MLP: k-split blocks (32 cols x 8 k-chunks) ----------------
__global__ void k_mod1(const float* __restrict__ mod, const float* __restrict__ w1,
                       const float* __restrict__ b1) {
    __shared__ float part[8][33];
    int c  = threadIdx.x & 31;
    int kw = threadIdx.x >> 5;
    int col = blockIdx.x * 32 + c;              // grid.x = 24
    int b   = blockIdx.y;                        // 8
    const float* mrow = mod + b * 768;
    float acc = 0.f;
    int k0 = kw * 96;
    #pragma unroll 8
    for (int k = 0; k < 96; k++)
        acc += __ldg(mrow + k0 + k) * __ldg(w1 + (size_t)(k0 + k)*768 + col);
    part[kw][c] = acc;
    __syncthreads();
    if (kw == 0) {
        float s = part[0][c];
        #pragma unroll
        for (int i = 1; i < 8; i++) s += part[i][c];
        float v = s + b1[col];
        g_hm[b*768 + col] = v / (1.f + expf(-v));
    }
}

__global__ void k_mod2(const float* __restrict__ w2, const float* __restrict__ b2) {
    __shared__ float part[8][33];
    int c  = threadIdx.x & 31;
    int kw = threadIdx.x >> 5;
    int col = blockIdx.x * 32 + c;              // grid.x = 144
    int b   = blockIdx.y;                        // 8
    const float* hrow = g_hm + b * 768;
    float acc = 0.f;
    int k0 = kw * 96;
    #pragma unroll 8
    for (int k = 0; k < 96; k++)
        acc += __ldg(hrow + k0 + k) * __ldg(w2 + (size_t)(k0 + k)*4608 + col);
    part[kw][c] = acc;
    __syncthreads();
    if (kw == 0) {
        float s = part[0][c];
        #pragma unroll
        for (int i = 1; i < 8; i++) s += part[i][c];
        g_m[b*4608 + col] = s + b2[col];
    }
}

// ---------------- LN1 + modulate + shift + window partition (192 thr, float4) ----------------
__global__ void k_ln1(const float* __restrict__ x) {
    int t = blockIdx.x;
    int b   = t >> 12;
    int win = (t >> 6) & 63;
    int l   = t & 63;
    int nh = win >> 3, nw = win & 7;
    int wi = l >> 3,  wj = l & 7;
    int si = (nh*8 + wi + 60) & 63;
    int sj = (nw*8 + wj + 60) & 63;
    const float* xr = x + (size_t)(b*4096 + si*64 + sj) * 768u;
    int tid = threadIdx.x;           // 0..191
    int c = tid * 4;
    float4 v = *(const float4*)(xr + c);
    float s  = v.x + v.y + v.z + v.w;
    float ss = v.x*v.x + v.y*v.y + v.z*v.z + v.w*v.w;
    block_reduce_192(s, ss);
    float mean = s * (1.f/768.f);
    float var  = (ss - s*mean) * (1.f/767.f);
    float inv  = rsqrtf(var + 1e-5f);
    const float* mb = g_m + b*4608;
    float4 a1 = *(const float4*)(mb + c);
    float4 b1 = *(const float4*)(mb + 768 + c);
    float o0 = (a1.x + 1.f) * (v.x - mean) * inv + b1.x;
    float o1 = (a1.y + 1.f) * (v.y - mean) * inv + b1.y;
    float o2 = (a1.z + 1.f) * (v.z - mean) * inv + b1.z;
    float o3 = (a1.w + 1.f) * (v.w - mean) * inv + b1.w;
    __nv_bfloat162 lo = __floats2bfloat162_rn(o0, o1);
    __nv_bfloat162 hi = __floats2bfloat162_rn(o2, o3);
    *(uint2*)(g_yw + (size_t)t*768u + c) = make_uint2(*(uint32_t*)&lo, *(uint32_t*)&hi);
}

// ---------------- residual1 + LN2 + modulate (192 thr, float4) ----------------
__global__ void k_resid_ln2(const float* __restrict__ x) {
    int p = blockIdx.x;
    int b = p >> 12;
    int i = (p >> 6) & 63, j = p & 63;
    int hh = (i+4) & 63, ww = (j+4) & 63;
    int t = (b*64 + (hh>>3)*8 + (ww>>3))*64 + (hh&7)*8 + (ww&7);
    const float* xr = x + (size_t)p*768u;
    const bf16* pr = g_po + (size_t)t*768u;
    const float* mb = g_m + b*4608;
    int tid = threadIdx.x;           // 0..191
    int c = tid * 4;
    float4 xv = *(const float4*)(xr + c);
    uint2 pu = *(const uint2*)(pr + c);
    __nv_bfloat162 pa = *reinterpret_cast<__nv_bfloat162*>(&pu.x);
    __nv_bfloat162 pb = *reinterpret_cast<__nv_bfloat162*>(&pu.y);
    float4 c1 = *(const float4*)(mb + 1536 + c);
    float y0 = (xv.x + c1.x * __bfloat162float(pa.x)) * rsqrtf(1.f + c1.x*c1.x);
    float y1 = (xv.y + c1.y * __bfloat162float(pa.y)) * rsqrtf(1.f + c1.y*c1.y);
    float y2 = (xv.z + c1.z * __bfloat162float(pb.x)) * rsqrtf(1.f + c1.z*c1.z);
    float y3 = (xv.w + c1.w * __bfloat162float(pb.y)) * rsqrtf(1.f + c1.w*c1.w);
    float s  = y0 + y1 + y2 + y3;
    float ss = y0*y0 + y1*y1 + y2*y2 + y3*y3;
    block_reduce_192(s, ss);
    float mean = s * (1.f/768.f);
    float var  = (ss - s*mean) * (1.f/767.f);
    float inv  = rsqrtf(var + 1e-5f);
    float4 a2 = *(const float4*)(mb + 2304 + c);
    float4 b2 = *(const float4*)(mb + 3072 + c);
    float o0 = (a2.x + 1.f) * (y0 - mean) * inv + b2.x;
    float o1 = (a2.y + 1.f) * (y1 - mean) * inv + b2.y;
    float o2 = (a2.z + 1.f) * (y2 - mean) * inv + b2.z;
    float o3 = (a2.w + 1.f) * (y3 - mean) * inv + b2.w;
    __nv_bfloat162 lo = __floats2bfloat162_rn(o0, o1);
    __nv_bfloat162 hi = __floats2bfloat162_rn(o2, o3);
    *(uint2*)(g_zin + (size_t)p*768u + c) = make_uint2(*(uint32_t*)&lo, *(uint32_t*)&hi);
}

// ---------------- pipelined wmma GEMM: C = A(MxK) @ B(KxN) + bias, epilogue ----------------
// 128x128 CTA tile, K-stage=32, 5-stage cp.async pipeline, 2x4 warp grid (64x32 per warp).
// Single-pass epilogue: full 128x132 fp32 C tile in smem (67.6KB <= 94.7KB), one barrier.
#define GSTAGE   18944                  // As 128x40x2 (10240) + Bs 32x136x2 (8704)
#define GEMM_SMEM (5*GSTAGE)            // 94720

template<int MODE>
__global__ void __launch_bounds__(256, 2)
k_gemm(const bf16* __restrict__ A, const bf16* __restrict__ B,
       const float* __restrict__ bias, void* __restrict__ Cout,
       int M, int N, int K, const float* __restrict__ xres) {
    extern __shared__ __align__(128) char dsm[];

    int tid = threadIdx.x;
    int warp = tid >> 5;
    int wr = warp >> 2, wc = warp & 3;      // 2 x 4 warp grid, warp tile 64x32
    int m0 = blockIdx.y * 128, n0 = blockIdx.x * 128;

    const bf16* Ag = A + (size_t)m0 * (size_t)K;

    int arow = tid >> 2;
    int ach  = (tid & 3) * 8;
    int brow = tid >> 4;
    int bch  = (tid & 15) * 8;

    uint32_t sbase = smem_u32(dsm);

    auto load_stage = [&](int buf, int k0) {
        uint32_t as = sbase + buf * GSTAGE;
        uint32_t bs = as + 10240;
        const bf16* Ap = Ag + k0 + ach;
        #pragma unroll
        for (int i = 0; i < 2; i++) {
            int r = arow + i*64;
            cpa16(as + (r*40 + ach)*2, Ap + (size_t)r * K);
        }
        #pragma unroll
        for (int i = 0; i < 2; i++) {
            int r = brow + i*16;
            cpa16(bs + (r*136 + bch)*2, B + (size_t)(k0 + r) * N + n0 + bch);
        }
    };

    wmma::fragment<wmma::accumulator, 16,16,16, float> acc[4][2];
    #pragma unroll
    for (int i = 0; i < 4; i++)
        #pragma unroll
        for (int j = 0; j < 2; j++)
            wmma::fill_fragment(acc[i][j], 0.f);

    int KS = K >> 5;
    load_stage(0, 0);   cpa_commit();
    load_stage(1, 32);  cpa_commit();
    load_stage(2, 64);  cpa_commit();
    load_stage(3, 96);  cpa_commit();

    for (int ks = 0; ks < KS; ks++) {
        asm volatile("cp.async.wait_group 3;" ::: "memory");
        __syncthreads();
        int buf = ks % 5;
        bf16* As = (bf16*)(dsm + buf * GSTAGE);
        bf16* Bs = (bf16*)(dsm + buf * GSTAGE + 10240);
        #pragma unroll
        for (int kk = 0; kk < 2; kk++) {
            wmma::fragment<wmma::matrix_a,16,16,16,bf16,wmma::row_major> af[4];
            wmma::fragment<wmma::matrix_b,16,16,16,bf16,wmma::row_major> bfr[2];
            #pragma unroll
            for (int i = 0; i < 4; i++)
                wmma::load_matrix_sync(af[i], &As[(wr*64 + 16*i)*40 + kk*16], 40);
            #pragma unroll
            for (int j = 0; j < 2; j++)
                wmma::load_matrix_sync(bfr[j], &Bs[(kk*16)*136 + wc*32 + 16*j], 136);
            #pragma unroll
            for (int i = 0; i < 4; i++)
                #pragma unroll
                for (int j = 0; j < 2; j++)
                    wmma::mma_sync(acc[i][j], af[i], bfr[j], acc[i][j]);
        }
        int t = ks + 4;
        if (t < KS) load_stage(t % 5, t * 32);
        cpa_commit();
    }
    __syncthreads();   // all warps done before smem reuse

    // ---- single-pass epilogue: full 128x132 fp32 tile, one barrier ----
    float* Cs = (float*)dsm;   // [128][132] = 67584 B
    #pragma unroll
    for (int i = 0; i < 4; i++)
        #pragma unroll
        for (int j = 0; j < 2; j++)
            wmma::store_matrix_sync(&Cs[(wr*64 + 16*i)*132 + wc*32 + 16*j], acc[i][j],
                                    132, wmma::mem_row_major);
    __syncthreads();

    {
        int r  = tid >> 1;                 // 0..127
        int cs = (tid & 1) * 64;           // 0 or 64
        int grow = m0 + r;
        const float* crow = &Cs[r*132];
        #pragma unroll 8
        for (int cc = 0; cc < 64; cc += 2) {
            int col = cs + cc, gcol = n0 + col;
            float v0 = crow[col]     + bias[gcol];
            float v1 = crow[col + 1] + bias[gcol + 1];
            if (MODE == 2) {
                v0 = v0 / (1.f + __expf(-v0));
                v1 = v1 / (1.f + __expf(-v1));
            }
            if (MODE == 3) {
                float c2a = g_m[(grow >> 12)*4608 + 3840 + gcol];
                float c2b = g_m[(grow >> 12)*4608 + 3840 + gcol + 1];
                float o0 = (xres[(size_t)grow*768u + gcol]     + c2a*v0) * rsqrtf(1.f + c2a*c2a);
                float o1 = (xres[(size_t)grow*768u + gcol + 1] + c2b*v1) * rsqrtf(1.f + c2b*c2b);
                *(float2*)((float*)Cout + (size_t)grow*(size_t)N + gcol) = make_float2(o0, o1);
            } else {
                *(__nv_bfloat162*)((bf16*)Cout + (size_t)grow*(size_t)N + gcol) =
                    __floats2bfloat162_rn(v0, v1);
            }
        }
    }
}

// ---------------- window attention: one block per (window, head) ----------------
__global__ void k_attn() {
    __shared__ __align__(128) char smem[35840];
    bf16*  qs = (bf16*)smem;                 // [64][48]
    bf16*  ks = (bf16*)(smem + 6144);        // [64][48]
    bf16*  vs = (bf16*)(smem + 12288);       // [64][48]
    float* Ss = (float*)(smem + 18432);      // [64][68]
    bf16*  Ps = (bf16*)smem;                 // [64][64]
    float* Os = (float*)(smem + 18432);      // [64][48]

    int blk = blockIdx.x;
    int w = blk >> 4, h = blk & 15;
    int tid = threadIdx.x, warp = tid >> 5;
    const float scale = 0.14433756729740643f;   // 1/sqrt(48)

    for (int idx = tid; idx < 1536; idx += 256) {
        int l = idx / 24, j = idx - l*24;
        size_t base = (size_t)(w*64 + l)*2304u + (size_t)h*48u;
        float qr = __bfloat162float(g_qkv[base + 2*j]);
        float qi = __bfloat162float(g_qkv[base + 2*j + 1]);
        float kr = __bfloat162float(g_qkv[base + 768 + 2*j]);
        float ki = __bfloat162float(g_qkv[base + 768 + 2*j + 1]);
        int ti = (h*64 + l)*24 + j;
        float cn = g_cos[ti], sn = g_sin[ti];
        qs[l*48 + 2*j]     = __float2bfloat16((qr*cn - qi*sn) * scale);
        qs[l*48 + 2*j + 1] = __float2bfloat16((qr*sn + qi*cn) * scale);
        ks[l*48 + 2*j]     = __float2bfloat16(kr*cn - ki*sn);
        ks[l*48 + 2*j + 1] = __float2bfloat16(kr*sn + ki*cn);
    }
    for (int idx = tid; idx < 3072; idx += 256) {
        int l = idx / 48, c = idx - l*48;
        vs[idx] = g_qkv[(size_t)(w*64 + l)*2304u + 1536u + h*48u + c];
    }
    __syncthreads();

    #pragma unroll
    for (int tset = 0; tset < 2; tset++) {
        int tile = warp + tset*8;
        int ti = tile >> 2, tj = tile & 3;
        wmma::fragment<wmma::accumulator,16,16,16,float> sacc;
        wmma::fill_fragment(sacc, 0.f);
        #pragma unroll
        for (int kk = 0; kk < 3; kk++) {
            wmma::fragment<wmma::matrix_a,16,16,16,bf16,wmma::row_major> af;
            wmma::fragment<wmma::matrix_b,16,16,16,bf16,wmma::col_major> bfr;
            wmma::load_matrix_sync(af,  &qs[ti*16*48 + kk*16], 48);
            wmma::load_matrix_sync(bfr, &ks[tj*16*48 + kk*16], 48);
            wmma::mma_sync(sacc, af, bfr, sacc);
        }
        wmma::store_matrix_sync(&Ss[ti*16*68 + tj*16], sacc, 68, wmma::mem_row_major);
    }
    __syncthreads();

    {
        int l = tid >> 2, sub = tid & 3;
        float* srow = &Ss[l*68];
        float mx = -1e30f;
        #pragma unroll
        for (int q = 0; q < 16; q++) mx = fmaxf(mx, srow[sub*16 + q]);
        mx = fmaxf(mx, __shfl_xor_sync(0xffffffffu, mx, 1));
        mx = fmaxf(mx, __shfl_xor_sync(0xffffffffu, mx, 2));
        float e[16]; float sum = 0.f;
        #pragma unroll
        for (int q = 0; q < 16; q++) { e[q] = __expf(srow[sub*16 + q] - mx); sum += e[q]; }
        sum += __shfl_xor_sync(0xffffffffu, sum, 1);
        sum += __shfl_xor_sync(0xffffffffu, sum, 2);
        float inv = 1.f / sum;
        #pragma unroll
        for (int q = 0; q < 16; q++)
            Ps[l*64 + sub*16 + q] = __float2bfloat16(e[q] * inv);
    }
    __syncthreads();

    for (int tile = warp; tile < 12; tile += 8) {
        int ti = tile / 3, tj = tile - ti*3;
        wmma::fragment<wmma::accumulator,16,16,16,float> oacc;
        wmma::fill_fragment(oacc, 0.f);
        #pragma unroll
        for (int kk = 0; kk < 4; kk++) {
            wmma::fragment<wmma::matrix_a,16,16,16,bf16,wmma::row_major> af;
            wmma::fragment<wmma::matrix_b,16,16,16,bf16,wmma::row_major> bfr;
            wmma::load_matrix_sync(af,  &Ps[ti*16*64 + kk*16], 64);
            wmma::load_matrix_sync(bfr, &vs[kk*16*48 + tj*16], 48);
            wmma::mma_sync(oacc, af, bfr, oacc);
        }
        wmma::store_matrix_sync(&Os[ti*16*48 + tj*16], oacc, 48, wmma::mem_row_major);
    }
    __syncthreads();

    for (int idx = tid; idx < 3072; idx += 256) {
        int l = idx / 48, c = idx - l*48;
        g_ow[(size_t)(w*64 + l)*768u + h*48u + c] = __float2bfloat16(Os[idx]);
    }
}

// ---------------- launch ----------------
extern "C" void kernel_launch(void* const* d_in, const int* in_sizes, int n_in,
                              void* d_out, int out_size) {
    const float* x       = (const float*)d_in[0];
    const float* mod     = (const float*)d_in[1];
    const float* ada_w1  = (const float*)d_in[2];
    const float* ada_b1  = (const float*)d_in[3];
    const float* ada_w2  = (const float*)d_in[4];
    const float* ada_b2  = (const float*)d_in[5];
    const float* theta   = (const float*)d_in[6];
    const float* qkv_w   = (const float*)d_in[7];
    const float* qkv_b   = (const float*)d_in[8];
    const float* proj_w  = (const float*)d_in[9];
    const float* proj_b  = (const float*)d_in[10];
    const float* mlp_w1  = (const float*)d_in[11];
    const float* mlp_b1  = (const float*)d_in[12];
    const float* mlp_w2  = (const float*)d_in[13];
    const float* mlp_b2  = (const float*)d_in[14];
    float* out = (float*)d_out;

    void *p_yw, *p_qkv, *p_ow, *p_po, *p_zin, *p_h1;
    void *p_wqkv, *p_wproj, *p_w1, *p_w2;
    cudaGetSymbolAddress(&p_yw,   g_yw);
    cudaGetSymbolAddress(&p_qkv,  g_qkv);
    cudaGetSymbolAddress(&p_ow,   g_ow);
    cudaGetSymbolAddress(&p_po,   g_po);
    cudaGetSymbolAddress(&p_zin,  g_zin);
    cudaGetSymbolAddress(&p_h1,   g_h1);
    cudaGetSymbolAddress(&p_wqkv, g_wqkv);
    cudaGetSymbolAddress(&p_wproj,g_wproj);
    cudaGetSymbolAddress(&p_w1,   g_w1);
    cudaGetSymbolAddress(&p_w2,   g_w2);

    static bool init_done = false;
    static cudaStream_t s2;
    static cudaEvent_t evF, evJ;
    if (!init_done) {
        cudaFuncSetAttribute(k_gemm<0>, cudaFuncAttributeMaxDynamicSharedMemorySize, GEMM_SMEM);
        cudaFuncSetAttribute(k_gemm<2>, cudaFuncAttributeMaxDynamicSharedMemorySize, GEMM_SMEM);
        cudaFuncSetAttribute(k_gemm<3>, cudaFuncAttributeMaxDynamicSharedMemorySize, GEMM_SMEM);
        cudaStreamCreateWithFlags(&s2, cudaStreamNonBlocking);
        cudaEventCreateWithFlags(&evF, cudaEventDisableTiming);
        cudaEventCreateWithFlags(&evJ, cudaEventDisableTiming);
        init_done = true;
    }

    // fork: side stream converts proj/mlp weights + rope table (round-10 topology)
    cudaEventRecord(evF, 0);
    cudaStreamWaitEvent(s2, evF, 0);
    k_cvt_rest<<<5184, 256, 0, s2>>>(proj_w, (bf16*)p_wproj, 768*768,
                                     mlp_w1, (bf16*)p_w1, 768*3072,
                                     mlp_w2, (bf16*)p_w2, 3072*768);
    k_rope_tab<<<96, 256, 0, s2>>>(theta);
    cudaEventRecord(evJ, s2);

    // main stream: qkv weights, modulation (k-split), LN1, qkv GEMM
    k_cvt_qkv<<<1728, 256>>>(qkv_w, (bf16*)p_wqkv, 768*2304);
    k_mod1<<<dim3(24, 8), 256>>>(mod, ada_w1, ada_b1);
    k_mod2<<<dim3(144, 8), 256>>>(ada_w2, ada_b2);
    k_ln1<<<32768, 192>>>(x);

    // qkv GEMM (32768x768)@(768x2304)
    k_gemm<0><<<dim3(18, 256), 256, GEMM_SMEM>>>((const bf16*)p_yw, (const bf16*)p_wqkv,
                                                 qkv_b, p_qkv, 32768, 2304, 768, nullptr);

    // join: attention needs rope table; proj/mlp need converted weights
    cudaStreamWaitEvent(0, evJ, 0);

    k_attn<<<8192, 256>>>();

    // proj: (32768x768)@(768x768)
    k_gemm<0><<<dim3(6, 256), 256, GEMM_SMEM>>>((const bf16*)p_ow, (const bf16*)p_wproj,
                                                proj_b, p_po, 32768, 768, 768, nullptr);
    k_resid_ln2<<<32768, 192>>>(x);

    // mlp1 + silu: (32768x768)@(768x3072)
    k_gemm<2><<<dim3(24, 256), 256, GEMM_SMEM>>>((const bf16*)p_zin, (const bf16*)p_w1,
                                                 mlp_b1, p_h1, 32768, 3072, 768, nullptr);
    // mlp2 + final residual: (32768x3072)@(3072x768)
    k_gemm<3><<<dim3(6, 256), 256, GEMM_SMEM>>>((const bf16*)p_h1, (const bf16*)p_w2,
                                                mlp_b2, out, 32768, 768, 3072, x);
}

// round 15
// speedup vs baseline: 1.0381x; 1.0327x over previous
#include <cuda_runtime.h>
#include <cuda_bf16.h>
#include <mma.h>
#include <cstdint>

using namespace nvcuda;
typedef __nv_bfloat16 bf16;

// ---------------- constants ----------------
// C=768, HEADS=16, CH=48, WIN=8x8, SHIFTED, EPS=1e-5
// B=8, 64x64 -> 32768 tokens, 512 windows x 64 tokens, 16 heads

// ---------------- scratch (device globals; no allocation allowed) ----------------
__device__ bf16  g_yw [32768u*768u];    // LN1-modulated, shifted+windowed, bf16
__device__ bf16  g_qkv[32768u*2304u];   // qkv output (windowed token order)
__device__ bf16  g_ow [32768u*768u];    // attention output (windowed, heads merged)
__device__ bf16  g_po [32768u*768u];    // proj output + bias (windowed)
__device__ bf16  g_zin[32768u*768u];    // LN2-modulated (pixel order)
__device__ bf16  g_h1 [32768u*3072u];   // mlp hidden (silu applied)
__device__ float g_hm [8*768];          // silu(mod@ada_w1+b1)
__device__ float g_m  [8*4608];         // modulation vectors a1,b1,c1,a2,b2,c2
__device__ bf16  g_wqkv [768*2304];
__device__ bf16  g_wproj[768*768];
__device__ bf16  g_w1   [768*3072];
__device__ bf16  g_w2   [3072*768];
__device__ float g_cos[16*64*24];
__device__ float g_sin[16*64*24];

// ---------------- helpers ----------------
__device__ __forceinline__ void block_reduce_192(float& s, float& ss) {
    #pragma unroll
    for (int o = 16; o > 0; o >>= 1) {
        s  += __shfl_xor_sync(0xffffffffu, s,  o);
        ss += __shfl_xor_sync(0xffffffffu, ss, o);
    }
    __shared__ float rs[6], rss[6];
    int warp = threadIdx.x >> 5;
    int lane = threadIdx.x & 31;
    if (lane == 0) { rs[warp] = s; rss[warp] = ss; }
    __syncthreads();
    float a = 0.f, b = 0.f;
    #pragma unroll
    for (int i = 0; i < 6; i++) { a += rs[i]; b += rss[i]; }
    s = a; ss = b;
}

__device__ __forceinline__ uint32_t smem_u32(const void* p) {
    uint32_t r;
    asm("{ .reg .u64 t; cvta.to.shared.u64 t, %1; cvt.u32.u64 %0, t; }" : "=r"(r) : "l"(p));
    return r;
}
__device__ __forceinline__ void cpa16(uint32_t s, const void* g) {
    asm volatile("cp.async.cg.shared.global [%0], [%1], 16;" :: "r"(s), "l"(g));
}
__device__ __forceinline__ void cpa_commit() { asm volatile("cp.async.commit_group;" ::: "memory"); }

// ---------------- weight conversion (vectorized, 4 elems/thread) ----------------
__device__ __forceinline__ void cvt4(const float* __restrict__ s, bf16* __restrict__ d, int i) {
    float4 v = *(const float4*)(s + i);
    __nv_bfloat162 lo = __floats2bfloat162_rn(v.x, v.y);
    __nv_bfloat162 hi = __floats2bfloat162_rn(v.z, v.w);
    *(uint2*)(d + i) = make_uint2(*(uint32_t*)&lo, *(uint32_t*)&hi);
}

__global__ void k_cvt_qkv(const float* __restrict__ s0, bf16* __restrict__ d0, int n0) {
    int i = (blockIdx.x * 256 + threadIdx.x) * 4;
    if (i < n0) cvt4(s0, d0, i);
}

__global__ void k_cvt_rest(const float* __restrict__ s1, bf16* __restrict__ d1, int n1,
                           const float* __restrict__ s2, bf16* __restrict__ d2, int n2,
                           const float* __restrict__ s3, bf16* __restrict__ d3, int n3) {
    int i = (blockIdx.x * 256 + threadIdx.x) * 4;
    if (i < n1) { cvt4(s1, d1, i); return; }
    i -= n1;
    if (i < n2) { cvt4(s2, d2, i); return; }
    i -= n2;
    if (i < n3) { cvt4(s3, d3, i); }
}

// ---------------- rope table ----------------
__global__ void k_rope_tab(const float* __restrict__ theta) {
    int i = blockIdx.x * 256 + threadIdx.x;   // < 16*64*24 = 24576
    if (i >= 16*64*24) return;
    int j = i % 24;
    int rem = i / 24;
    int l = rem & 63;
    int h = rem >> 6;
    int f = h*24 + j;
    float th = (float)(l >> 3) * theta[f] + (float)(l & 7) * theta[384 + f];
    float s, c;
    sincosf(th, &s, &c);
    g_cos[i] = c; g_sin[i] = s;
}

// ---------------- modulation MLP: k-split blocks (32 cols x 8 k-chunks) ----------------
__global__ void k_mod1(const float* __restrict__ mod, const float* __restrict__ w1,
                       const float* __restrict__ b1) {
    __shared__ float part[8][33];
    int c  = threadIdx.x & 31;
    int kw = threadIdx.x >> 5;
    int col = blockIdx.x * 32 + c;              // grid.x = 24
    int b   = blockIdx.y;                        // 8
    const float* mrow = mod + b * 768;
    float acc = 0.f;
    int k0 = kw * 96;
    #pragma unroll 8
    for (int k = 0; k < 96; k++)
        acc += __ldg(mrow + k0 + k) * __ldg(w1 + (size_t)(k0 + k)*768 + col);
    part[kw][c] = acc;
    __syncthreads();
    if (kw == 0) {
        float s = part[0][c];
        #pragma unroll
        for (int i = 1; i < 8; i++) s += part[i][c];
        float v = s + b1[col];
        g_hm[b*768 + col] = v / (1.f + expf(-v));
    }
}

__global__ void k_mod2(const float* __restrict__ w2, const float* __restrict__ b2) {
    __shared__ float part[8][33];
    int c  = threadIdx.x & 31;
    int kw = threadIdx.x >> 5;
    int col = blockIdx.x * 32 + c;              // grid.x = 144
    int b   = blockIdx.y;                        // 8
    const float* hrow = g_hm + b * 768;
    float acc = 0.f;
    int k0 = kw * 96;
    #pragma unroll 8
    for (int k = 0; k < 96; k++)
        acc += __ldg(hrow + k0 + k) * __ldg(w2 + (size_t)(k0 + k)*4608 + col);
    part[kw][c] = acc;
    __syncthreads();
    if (kw == 0) {
        float s = part[0][c];
        #pragma unroll
        for (int i = 1; i < 8; i++) s += part[i][c];
        g_m[b*4608 + col] = s + b2[col];
    }
}

// ---------------- LN1 + modulate + shift + window partition (192 thr, float4) ----------------
__global__ void k_ln1(const float* __restrict__ x) {
    int t = blockIdx.x;
    int b   = t >> 12;
    int win = (t >> 6) & 63;
    int l   = t & 63;
    int nh = win >> 3, nw = win & 7;
    int wi = l >> 3,  wj = l & 7;
    int si = (nh*8 + wi + 60) & 63;
    int sj = (nw*8 + wj + 60) & 63;
    const float* xr = x + (size_t)(b*4096 + si*64 + sj) * 768u;
    int tid = threadIdx.x;           // 0..191
    int c = tid * 4;
    float4 v = *(const float4*)(xr + c);
    float s  = v.x + v.y + v.z + v.w;
    float ss = v.x*v.x + v.y*v.y + v.z*v.z + v.w*v.w;
    block_reduce_192(s, ss);
    float mean = s * (1.f/768.f);
    float var  = (ss - s*mean) * (1.f/767.f);
    float inv  = rsqrtf(var + 1e-5f);
    const float* mb = g_m + b*4608;
    float4 a1 = *(const float4*)(mb + c);
    float4 b1 = *(const float4*)(mb + 768 + c);
    float o0 = (a1.x + 1.f) * (v.x - mean) * inv + b1.x;
    float o1 = (a1.y + 1.f) * (v.y - mean) * inv + b1.y;
    float o2 = (a1.z + 1.f) * (v.z - mean) * inv + b1.z;
    float o3 = (a1.w + 1.f) * (v.w - mean) * inv + b1.w;
    __nv_bfloat162 lo = __floats2bfloat162_rn(o0, o1);
    __nv_bfloat162 hi = __floats2bfloat162_rn(o2, o3);
    *(uint2*)(g_yw + (size_t)t*768u + c) = make_uint2(*(uint32_t*)&lo, *(uint32_t*)&hi);
}

// ---------------- residual1 + LN2 + modulate (192 thr, float4) ----------------
__global__ void k_resid_ln2(const float* __restrict__ x) {
    int p = blockIdx.x;
    int b = p >> 12;
    int i = (p >> 6) & 63, j = p & 63;
    int hh = (i+4) & 63, ww = (j+4) & 63;
    int t = (b*64 + (hh>>3)*8 + (ww>>3))*64 + (hh&7)*8 + (ww&7);
    const float* xr = x + (size_t)p*768u;
    const bf16* pr = g_po + (size_t)t*768u;
    const float* mb = g_m + b*4608;
    int tid = threadIdx.x;           // 0..191
    int c = tid * 4;
    float4 xv = *(const float4*)(xr + c);
    uint2 pu = *(const uint2*)(pr + c);
    __nv_bfloat162 pa = *reinterpret_cast<__nv_bfloat162*>(&pu.x);
    __nv_bfloat162 pb = *reinterpret_cast<__nv_bfloat162*>(&pu.y);
    float4 c1 = *(const float4*)(mb + 1536 + c);
    float y0 = (xv.x + c1.x * __bfloat162float(pa.x)) * rsqrtf(1.f + c1.x*c1.x);
    float y1 = (xv.y + c1.y * __bfloat162float(pa.y)) * rsqrtf(1.f + c1.y*c1.y);
    float y2 = (xv.z + c1.z * __bfloat162float(pb.x)) * rsqrtf(1.f + c1.z*c1.z);
    float y3 = (xv.w + c1.w * __bfloat162float(pb.y)) * rsqrtf(1.f + c1.w*c1.w);
    float s  = y0 + y1 + y2 + y3;
    float ss = y0*y0 + y1*y1 + y2*y2 + y3*y3;
    block_reduce_192(s, ss);
    float mean = s * (1.f/768.f);
    float var  = (ss - s*mean) * (1.f/767.f);
    float inv  = rsqrtf(var + 1e-5f);
    float4 a2 = *(const float4*)(mb + 2304 + c);
    float4 b2 = *(const float4*)(mb + 3072 + c);
    float o0 = (a2.x + 1.f) * (y0 - mean) * inv + b2.x;
    float o1 = (a2.y + 1.f) * (y1 - mean) * inv + b2.y;
    float o2 = (a2.z + 1.f) * (y2 - mean) * inv + b2.z;
    float o3 = (a2.w + 1.f) * (y3 - mean) * inv + b2.w;
    __nv_bfloat162 lo = __floats2bfloat162_rn(o0, o1);
    __nv_bfloat162 hi = __floats2bfloat162_rn(o2, o3);
    *(uint2*)(g_zin + (size_t)p*768u + c) = make_uint2(*(uint32_t*)&lo, *(uint32_t*)&hi);
}

// ---------------- pipelined wmma GEMM: C = A(MxK) @ B(KxN) + bias, epilogue ----------------
// 128x128 CTA tile, K-stage=32, 5-stage cp.async pipeline, 2x4 warp grid (64x32 per warp).
#define GSTAGE   18944                  // As 128x40x2 (10240) + Bs 32x136x2 (8704)
#define GEMM_SMEM (5*GSTAGE)            // 94720

template<int MODE>
__global__ void __launch_bounds__(256, 2)
k_gemm(const bf16* __restrict__ A, const bf16* __restrict__ B,
       const float* __restrict__ bias, void* __restrict__ Cout,
       int M, int N, int K, const float* __restrict__ xres) {
    extern __shared__ __align__(128) char dsm[];

    int tid = threadIdx.x;
    int warp = tid >> 5;
    int wr = warp >> 2, wc = warp & 3;      // 2 x 4 warp grid, warp tile 64x32
    int m0 = blockIdx.y * 128, n0 = blockIdx.x * 128;

    const bf16* Ag = A + (size_t)m0 * (size_t)K;

    int arow = tid >> 2;
    int ach  = (tid & 3) * 8;
    int brow = tid >> 4;
    int bch  = (tid & 15) * 8;

    uint32_t sbase = smem_u32(dsm);

    auto load_stage = [&](int buf, int k0) {
        uint32_t as = sbase + buf * GSTAGE;
        uint32_t bs = as + 10240;
        const bf16* Ap = Ag + k0 + ach;
        #pragma unroll
        for (int i = 0; i < 2; i++) {
            int r = arow + i*64;
            cpa16(as + (r*40 + ach)*2, Ap + (size_t)r * K);
        }
        #pragma unroll
        for (int i = 0; i < 2; i++) {
            int r = brow + i*16;
            cpa16(bs + (r*136 + bch)*2, B + (size_t)(k0 + r) * N + n0 + bch);
        }
    };

    wmma::fragment<wmma::accumulator, 16,16,16, float> acc[4][2];
    #pragma unroll
    for (int i = 0; i < 4; i++)
        #pragma unroll
        for (int j = 0; j < 2; j++)
            wmma::fill_fragment(acc[i][j], 0.f);

    int KS = K >> 5;
    load_stage(0, 0);   cpa_commit();
    load_stage(1, 32);  cpa_commit();
    load_stage(2, 64);  cpa_commit();
    load_stage(3, 96);  cpa_commit();

    for (int ks = 0; ks < KS; ks++) {
        asm volatile("cp.async.wait_group 3;" ::: "memory");
        __syncthreads();
        int buf = ks % 5;
        bf16* As = (bf16*)(dsm + buf * GSTAGE);
        bf16* Bs = (bf16*)(dsm + buf * GSTAGE + 10240);
        #pragma unroll
        for (int kk = 0; kk < 2; kk++) {
            wmma::fragment<wmma::matrix_a,16,16,16,bf16,wmma::row_major> af[4];
            wmma::fragment<wmma::matrix_b,16,16,16,bf16,wmma::row_major> bfr[2];
            #pragma unroll
            for (int i = 0; i < 4; i++)
                wmma::load_matrix_sync(af[i], &As[(wr*64 + 16*i)*40 + kk*16], 40);
            #pragma unroll
            for (int j = 0; j < 2; j++)
                wmma::load_matrix_sync(bfr[j], &Bs[(kk*16)*136 + wc*32 + 16*j], 136);
            #pragma unroll
            for (int i = 0; i < 4; i++)
                #pragma unroll
                for (int j = 0; j < 2; j++)
                    wmma::mma_sync(acc[i][j], af[i], bfr[j], acc[i][j]);
        }
        int t = ks + 4;
        if (t < KS) load_stage(t % 5, t * 32);
        cpa_commit();
    }
    __syncthreads();

    // epilogue via smem: two halves (R12 layout)
    float* Cs = (float*)dsm;   // [64][132]
    #pragma unroll
    for (int half = 0; half < 2; half++) {
        if (wr == half) {
            #pragma unroll
            for (int i = 0; i < 4; i++)
                #pragma unroll
                for (int j = 0; j < 2; j++)
                    wmma::store_matrix_sync(&Cs[(16*i)*132 + wc*32 + 16*j], acc[i][j],
                                            132, wmma::mem_row_major);
        }
        __syncthreads();
        int r  = tid >> 2;
        int cs = (tid & 3) * 32;
        int grow = m0 + half*64 + r;
        #pragma unroll 4
        for (int cc = 0; cc < 32; cc += 2) {
            int col = cs + cc, gcol = n0 + col;
            float v0 = Cs[r*132 + col]     + bias[gcol];
            float v1 = Cs[r*132 + col + 1] + bias[gcol + 1];
            if (MODE == 2) {
                v0 = v0 / (1.f + __expf(-v0));
                v1 = v1 / (1.f + __expf(-v1));
            }
            if (MODE == 3) {
                float c2a = g_m[(grow >> 12)*4608 + 3840 + gcol];
                float c2b = g_m[(grow >> 12)*4608 + 3840 + gcol + 1];
                float o0 = (xres[(size_t)grow*768u + gcol]     + c2a*v0) * rsqrtf(1.f + c2a*c2a);
                float o1 = (xres[(size_t)grow*768u + gcol + 1] + c2b*v1) * rsqrtf(1.f + c2b*c2b);
                *(float2*)((float*)Cout + (size_t)grow*(size_t)N + gcol) = make_float2(o0, o1);
            } else {
                *(__nv_bfloat162*)((bf16*)Cout + (size_t)grow*(size_t)N + gcol) =
                    __floats2bfloat162_rn(v0, v1);
            }
        }
        __syncthreads();
    }
}

// ---------------- window attention: one block per (window, head), vectorized I/O ----------------
__global__ void k_attn() {
    __shared__ __align__(128) char smem[35840];
    bf16*  qs = (bf16*)smem;                 // [64][48]
    bf16*  ks = (bf16*)(smem + 6144);        // [64][48]
    bf16*  vs = (bf16*)(smem + 12288);       // [64][48]
    float* Ss = (float*)(smem + 18432);      // [64][68]
    bf16*  Ps = (bf16*)smem;                 // [64][64]
    float* Os = (float*)(smem + 18432);      // [64][48]

    int blk = blockIdx.x;
    int w = blk >> 4, h = blk & 15;
    int tid = threadIdx.x, warp = tid >> 5;
    const float scale = 0.14433756729740643f;   // 1/sqrt(48)

    // q/k: one uint32 (bf16x2 complex pair) per load; rope; bf16x2 stores
    for (int idx = tid; idx < 1536; idx += 256) {
        int l = idx / 24, j = idx - l*24;
        const bf16* gp = g_qkv + (size_t)(w*64 + l)*2304u + (size_t)h*48u + 2*j;
        uint32_t qu = *(const uint32_t*)gp;
        uint32_t ku = *(const uint32_t*)(gp + 768);
        __nv_bfloat162 qp = *reinterpret_cast<__nv_bfloat162*>(&qu);
        __nv_bfloat162 kp = *reinterpret_cast<__nv_bfloat162*>(&ku);
        float qr = __bfloat162float(qp.x), qi = __bfloat162float(qp.y);
        float kr = __bfloat162float(kp.x), ki = __bfloat162float(kp.y);
        int ti = (h*64 + l)*24 + j;
        float cn = g_cos[ti], sn = g_sin[ti];
        __nv_bfloat162 qo = __floats2bfloat162_rn((qr*cn - qi*sn) * scale,
                                                  (qr*sn + qi*cn) * scale);
        __nv_bfloat162 ko = __floats2bfloat162_rn(kr*cn - ki*sn,
                                                  kr*sn + ki*cn);
        *(uint32_t*)(qs + l*48 + 2*j) = *(uint32_t*)&qo;
        *(uint32_t*)(ks + l*48 + 2*j) = *(uint32_t*)&ko;
    }
    // v: uint2 (4 bf16) per load; 64 rows x 12 chunks = 768
    for (int idx = tid; idx < 768; idx += 256) {
        int l = idx / 12, c4 = (idx - l*12) * 4;
        uint2 v = *(const uint2*)(g_qkv + (size_t)(w*64 + l)*2304u + 1536u + h*48u + c4);
        *(uint2*)(vs + l*48 + c4) = v;
    }
    __syncthreads();

    #pragma unroll
    for (int tset = 0; tset < 2; tset++) {
        int tile = warp + tset*8;
        int ti = tile >> 2, tj = tile & 3;
        wmma::fragment<wmma::accumulator,16,16,16,float> sacc;
        wmma::fill_fragment(sacc, 0.f);
        #pragma unroll
        for (int kk = 0; kk < 3; kk++) {
            wmma::fragment<wmma::matrix_a,16,16,16,bf16,wmma::row_major> af;
            wmma::fragment<wmma::matrix_b,16,16,16,bf16,wmma::col_major> bfr;
            wmma::load_matrix_sync(af,  &qs[ti*16*48 + kk*16], 48);
            wmma::load_matrix_sync(bfr, &ks[tj*16*48 + kk*16], 48);
            wmma::mma_sync(sacc, af, bfr, sacc);
        }
        wmma::store_matrix_sync(&Ss[ti*16*68 + tj*16], sacc, 68, wmma::mem_row_major);
    }
    __syncthreads();

    {
        int l = tid >> 2, sub = tid & 3;
        float* srow = &Ss[l*68];
        float mx = -1e30f;
        #pragma unroll
        for (int q = 0; q < 16; q++) mx = fmaxf(mx, srow[sub*16 + q]);
        mx = fmaxf(mx, __shfl_xor_sync(0xffffffffu, mx, 1));
        mx = fmaxf(mx, __shfl_xor_sync(0xffffffffu, mx, 2));
        float e[16]; float sum = 0.f;
        #pragma unroll
        for (int q = 0; q < 16; q++) { e[q] = __expf(srow[sub*16 + q] - mx); sum += e[q]; }
        sum += __shfl_xor_sync(0xffffffffu, sum, 1);
        sum += __shfl_xor_sync(0xffffffffu, sum, 2);
        float inv = 1.f / sum;
        #pragma unroll
        for (int q = 0; q < 16; q += 2) {
            __nv_bfloat162 pp = __floats2bfloat162_rn(e[q] * inv, e[q+1] * inv);
            *(uint32_t*)(Ps + l*64 + sub*16 + q) = *(uint32_t*)&pp;
        }
    }
    __syncthreads();

    for (int tile = warp; tile < 12; tile += 8) {
        int ti = tile / 3, tj = tile - ti*3;
        wmma::fragment<wmma::accumulator,16,16,16,float> oacc;
        wmma::fill_fragment(oacc, 0.f);
        #pragma unroll
        for (int kk = 0; kk < 4; kk++) {
            wmma::fragment<wmma::matrix_a,16,16,16,bf16,wmma::row_major> af;
            wmma::fragment<wmma::matrix_b,16,16,16,bf16,wmma::row_major> bfr;
            wmma::load_matrix_sync(af,  &Ps[ti*16*64 + kk*16], 64);
            wmma::load_matrix_sync(bfr, &vs[kk*16*48 + tj*16], 48);
            wmma::mma_sync(oacc, af, bfr, oacc);
        }
        wmma::store_matrix_sync(&Os[ti*16*48 + tj*16], oacc, 48, wmma::mem_row_major);
    }
    __syncthreads();

    // output: 4 floats -> uint2 (4 bf16) store; 64 rows x 12 chunks = 768
    for (int idx = tid; idx < 768; idx += 256) {
        int l = idx / 12, c4 = (idx - l*12) * 4;
        const float* orow = &Os[l*48 + c4];
        __nv_bfloat162 lo = __floats2bfloat162_rn(orow[0], orow[1]);
        __nv_bfloat162 hi = __floats2bfloat162_rn(orow[2], orow[3]);
        *(uint2*)(g_ow + (size_t)(w*64 + l)*768u + h*48u + c4) =
            make_uint2(*(uint32_t*)&lo, *(uint32_t*)&hi);
    }
}

// ---------------- launch ----------------
extern "C" void kernel_launch(void* const* d_in, const int* in_sizes, int n_in,
                              void* d_out, int out_size) {
    const float* x       = (const float*)d_in[0];
    const float* mod     = (const float*)d_in[1];
    const float* ada_w1  = (const float*)d_in[2];
    const float* ada_b1  = (const float*)d_in[3];
    const float* ada_w2  = (const float*)d_in[4];
    const float* ada_b2  = (const float*)d_in[5];
    const float* theta   = (const float*)d_in[6];
    const float* qkv_w   = (const float*)d_in[7];
    const float* qkv_b   = (const float*)d_in[8];
    const float* proj_w  = (const float*)d_in[9];
    const float* proj_b  = (const float*)d_in[10];
    const float* mlp_w1  = (const float*)d_in[11];
    const float* mlp_b1  = (const float*)d_in[12];
    const float* mlp_w2  = (const float*)d_in[13];
    const float* mlp_b2  = (const float*)d_in[14];
    float* out = (float*)d_out;

    void *p_yw, *p_qkv, *p_ow, *p_po, *p_zin, *p_h1;
    void *p_wqkv, *p_wproj, *p_w1, *p_w2;
    cudaGetSymbolAddress(&p_yw,   g_yw);
    cudaGetSymbolAddress(&p_qkv,  g_qkv);
    cudaGetSymbolAddress(&p_ow,   g_ow);
    cudaGetSymbolAddress(&p_po,   g_po);
    cudaGetSymbolAddress(&p_zin,  g_zin);
    cudaGetSymbolAddress(&p_h1,   g_h1);
    cudaGetSymbolAddress(&p_wqkv, g_wqkv);
    cudaGetSymbolAddress(&p_wproj,g_wproj);
    cudaGetSymbolAddress(&p_w1,   g_w1);
    cudaGetSymbolAddress(&p_w2,   g_w2);

    static bool init_done = false;
    static cudaStream_t s2;
    static cudaEvent_t evF, evJ;
    if (!init_done) {
        cudaFuncSetAttribute(k_gemm<0>, cudaFuncAttributeMaxDynamicSharedMemorySize, GEMM_SMEM);
        cudaFuncSetAttribute(k_gemm<2>, cudaFuncAttributeMaxDynamicSharedMemorySize, GEMM_SMEM);
        cudaFuncSetAttribute(k_gemm<3>, cudaFuncAttributeMaxDynamicSharedMemorySize, GEMM_SMEM);
        cudaStreamCreateWithFlags(&s2, cudaStreamNonBlocking);
        cudaEventCreateWithFlags(&evF, cudaEventDisableTiming);
        cudaEventCreateWithFlags(&evJ, cudaEventDisableTiming);
        init_done = true;
    }

    // fork: side stream converts proj/mlp weights + rope table (round-10 topology)
    cudaEventRecord(evF, 0);
    cudaStreamWaitEvent(s2, evF, 0);
    k_cvt_rest<<<5184, 256, 0, s2>>>(proj_w, (bf16*)p_wproj, 768*768,
                                     mlp_w1, (bf16*)p_w1, 768*3072,
                                     mlp_w2, (bf16*)p_w2, 3072*768);
    k_rope_tab<<<96, 256, 0, s2>>>(theta);
    cudaEventRecord(evJ, s2);

    // main stream: qkv weights, modulation (k-split), LN1, qkv GEMM
    k_cvt_qkv<<<1728, 256>>>(qkv_w, (bf16*)p_wqkv, 768*2304);
    k_mod1<<<dim3(24, 8), 256>>>(mod, ada_w1, ada_b1);
    k_mod2<<<dim3(144, 8), 256>>>(ada_w2, ada_b2);
    k_ln1<<<32768, 192>>>(x);

    // qkv GEMM (32768x768)@(768x2304)
    k_gemm<0><<<dim3(18, 256), 256, GEMM_SMEM>>>((const bf16*)p_yw, (const bf16*)p_wqkv,
                                                 qkv_b, p_qkv, 32768, 2304, 768, nullptr);

    // join: attention needs rope table; proj/mlp need converted weights
    cudaStreamWaitEvent(0, evJ, 0);

    k_attn<<<8192, 256>>>();

    // proj: (32768x768)@(768x768)
    k_gemm<0><<<dim3(6, 256), 256, GEMM_SMEM>>>((const bf16*)p_ow, (const bf16*)p_wproj,
                                                proj_b, p_po, 32768, 768, 768, nullptr);
    k_resid_ln2<<<32768, 192>>>(x);

    // mlp1 + silu: (32768x768)@(768x3072)
    k_gemm<2><<<dim3(24, 256), 256, GEMM_SMEM>>>((const bf16*)p_zin, (const bf16*)p_w1,
                                                 mlp_b1, p_h1, 32768, 3072, 768, nullptr);
    // mlp2 + final residual: (32768x3072)@(3072x768)
    k_gemm<3><<<dim3(6, 256), 256, GEMM_SMEM>>>((const bf16*)p_h1, (const bf16*)p_w2,
                                                mlp_b2, out, 32768, 768, 3072, x);
}